// round 1
// baseline (speedup 1.0000x reference)
#include <cuda_runtime.h>
#include <cuda_bf16.h>
#include <cstdint>

// Problem constants
#define BATCH 4096
#define DIM   768
#define FEAT  16384
#define TOPK  64

// ---------------- scratch (device globals; no allocation allowed) ----------
__device__ float g_xc[BATCH * DIM];                       // x - b_dec   (12.6 MB)
__device__ float g_pre[(size_t)BATCH * FEAT];             // pre-activations (256 MB)
__device__ float g_WdT[(size_t)FEAT * DIM];               // W_dec transposed (50 MB)
__device__ int   g_tidx[BATCH * TOPK];
__device__ float g_tval[BATCH * TOPK];

// ---------------- helpers --------------------------------------------------
__device__ __forceinline__ unsigned fkey(float v) {
    unsigned u = __float_as_uint(v);
    return (u & 0x80000000u) ? ~u : (u | 0x80000000u);   // monotonic increasing key
}
__device__ __forceinline__ float key_to_float(unsigned k) {
    unsigned u = (k & 0x80000000u) ? (k & 0x7fffffffu) : ~k;
    return __uint_as_float(u);
}

// ---------------- kernel 1: xc = x - b_dec ---------------------------------
__global__ void __launch_bounds__(256) sub_bdec_kernel(const float* __restrict__ x,
                                                       const float* __restrict__ b_dec) {
    int i = blockIdx.x * 256 + threadIdx.x;
    if (i < BATCH * DIM) g_xc[i] = x[i] - b_dec[i % DIM];
}

// ---------------- kernel 2: transpose W_dec [D,F] -> [F,D] -----------------
__global__ void transpose_wdec_kernel(const float* __restrict__ Wd) {
    __shared__ float tile[32][33];
    int f0 = blockIdx.x * 32;
    int d0 = blockIdx.y * 32;
    int tx = threadIdx.x, ty = threadIdx.y;   // block (32, 8)
    #pragma unroll
    for (int i = 0; i < 32; i += 8)
        tile[ty + i][tx] = Wd[(size_t)(d0 + ty + i) * FEAT + f0 + tx];
    __syncthreads();
    #pragma unroll
    for (int i = 0; i < 32; i += 8)
        g_WdT[(size_t)(f0 + ty + i) * DIM + d0 + tx] = tile[tx][ty + i];
}

// ---------------- kernel 3: encode GEMM ------------------------------------
// C[m,n] = sum_k xc[m,k] * W_enc[n,k] + b_enc[n]
// 128x128 tile, BK=16, 256 threads, 8x8 micro-tile.
#define GBM 128
#define GBN 128
#define GBK 16

__global__ void __launch_bounds__(256, 1) encode_gemm_kernel(
    const float* __restrict__ Bw,      // W_enc [FEAT, DIM]
    const float* __restrict__ bias)    // b_enc [FEAT]
{
    __shared__ float As[GBK][GBM];
    __shared__ float Bs[GBK][GBN];

    const int tid = threadIdx.x;
    const int m0 = blockIdx.y * GBM;
    const int n0 = blockIdx.x * GBN;
    const int tx = tid & 15;       // n-quad index
    const int ty = tid >> 4;       // m-quad index
    const int lrow = tid & 127;    // tile row for loading
    const int lcg  = (tid >> 7) * 2;  // column-group base (0 or 2)

    const float* Ap = g_xc + (size_t)(m0 + lrow) * DIM;
    const float* Bp = Bw   + (size_t)(n0 + lrow) * DIM;

    float acc[8][8];
    #pragma unroll
    for (int i = 0; i < 8; i++)
        #pragma unroll
        for (int j = 0; j < 8; j++) acc[i][j] = 0.f;

    for (int k0 = 0; k0 < DIM; k0 += GBK) {
        #pragma unroll
        for (int s = 0; s < 2; s++) {
            const int cg = lcg + s;
            float4 av = *(const float4*)(Ap + k0 + cg * 4);
            float4 bv = *(const float4*)(Bp + k0 + cg * 4);
            As[cg * 4 + 0][lrow] = av.x;
            As[cg * 4 + 1][lrow] = av.y;
            As[cg * 4 + 2][lrow] = av.z;
            As[cg * 4 + 3][lrow] = av.w;
            Bs[cg * 4 + 0][lrow] = bv.x;
            Bs[cg * 4 + 1][lrow] = bv.y;
            Bs[cg * 4 + 2][lrow] = bv.z;
            Bs[cg * 4 + 3][lrow] = bv.w;
        }
        __syncthreads();
        #pragma unroll
        for (int kk = 0; kk < GBK; kk++) {
            float ra[8], rb[8];
            *(float4*)&ra[0] = *(const float4*)&As[kk][ty * 4];
            *(float4*)&ra[4] = *(const float4*)&As[kk][64 + ty * 4];
            *(float4*)&rb[0] = *(const float4*)&Bs[kk][tx * 4];
            *(float4*)&rb[4] = *(const float4*)&Bs[kk][64 + tx * 4];
            #pragma unroll
            for (int i = 0; i < 8; i++)
                #pragma unroll
                for (int j = 0; j < 8; j++)
                    acc[i][j] += ra[i] * rb[j];
        }
        __syncthreads();
    }

    #pragma unroll
    for (int i = 0; i < 8; i++) {
        int mi = (i < 4) ? (ty * 4 + i) : (64 + ty * 4 + (i - 4));
        float* crow = g_pre + (size_t)(m0 + mi) * FEAT + n0;
        #pragma unroll
        for (int j = 0; j < 8; j++) {
            int nj = (j < 4) ? (tx * 4 + j) : (64 + tx * 4 + (j - 4));
            crow[nj] = acc[i][j] + bias[n0 + nj];
        }
    }
}

// ---------------- kernel 4: exact top-64 per row (radix select) ------------
__global__ void __launch_bounds__(256) topk_kernel() {
    const int row = blockIdx.x;
    const float* p = g_pre + (size_t)row * FEAT;
    const int tid = threadIdx.x;

    __shared__ unsigned hist[2048];
    __shared__ unsigned sh_digit, sh_need;
    __shared__ int cnt, eqn;
    __shared__ int eqbuf[256];

    unsigned prefix = 0;
    unsigned need = TOPK;

    const int shifts[3]  = {21, 10, 0};
    const int bitsArr[3] = {11, 11, 10};

    for (int lvl = 0; lvl < 3; lvl++) {
        const int shift = shifts[lvl];
        const int nb = 1 << bitsArr[lvl];
        for (int i = tid; i < 2048; i += 256) hist[i] = 0;
        __syncthreads();
        for (int i = tid; i < FEAT; i += 256) {
            unsigned key = fkey(p[i]);
            bool ok = (lvl == 0) || ((key >> (shift + bitsArr[lvl])) == prefix);
            if (ok) atomicAdd(&hist[(key >> shift) & (nb - 1)], 1u);
        }
        __syncthreads();
        if (tid == 0) {
            unsigned cum = 0, dig = 0, rem = need;
            for (int b = nb - 1; b >= 0; b--) {
                unsigned h = hist[b];
                if (cum + h >= need) { dig = (unsigned)b; rem = need - cum; break; }
                cum += h;
            }
            sh_digit = dig;
            sh_need = rem;
        }
        __syncthreads();
        prefix = (prefix << bitsArr[lvl]) | sh_digit;
        need = sh_need;
        __syncthreads();
    }

    const unsigned T = prefix;   // exact key of the K-th largest value
    if (tid == 0) { cnt = 0; eqn = 0; }
    __syncthreads();

    for (int i = tid; i < FEAT; i += 256) {
        unsigned key = fkey(p[i]);
        if (key > T) {
            int s = atomicAdd(&cnt, 1);
            g_tidx[row * TOPK + s] = i;
            g_tval[row * TOPK + s] = p[i];
        } else if (key == T) {
            int e = atomicAdd(&eqn, 1);
            if (e < 256) eqbuf[e] = i;
        }
    }
    __syncthreads();

    if (tid == 0) {
        int ne = eqn; if (ne > 256) ne = 256;
        // smallest-index tie-break (matches jax top_k), tiny N
        for (int a = 1; a < ne; a++) {
            int v = eqbuf[a]; int b = a - 1;
            while (b >= 0 && eqbuf[b] > v) { eqbuf[b + 1] = eqbuf[b]; b--; }
            eqbuf[b + 1] = v;
        }
        float tv = key_to_float(T);
        int base = cnt;                       // == TOPK - need by construction
        for (int j = 0; j < (int)need; j++) {
            g_tidx[row * TOPK + base + j] = eqbuf[j];
            g_tval[row * TOPK + base + j] = tv;
        }
    }
}

// ---------------- kernel 5: sparse decode ----------------------------------
__global__ void __launch_bounds__(256) decode_kernel(const float* __restrict__ b_dec,
                                                     float* __restrict__ out) {
    const int row = blockIdx.x;
    const int t = threadIdx.x;
    __shared__ int   sidx[TOPK];
    __shared__ float sval[TOPK];
    if (t < TOPK) {
        sidx[t] = g_tidx[row * TOPK + t];
        sval[t] = g_tval[row * TOPK + t];
    }
    __syncthreads();

    float a0 = b_dec[t];
    float a1 = b_dec[t + 256];
    float a2 = b_dec[t + 512];
    #pragma unroll 4
    for (int k = 0; k < TOPK; k++) {
        const float* w = g_WdT + (size_t)sidx[k] * DIM;
        float v = sval[k];
        a0 += v * w[t];
        a1 += v * w[t + 256];
        a2 += v * w[t + 512];
    }
    float* o = out + (size_t)row * DIM;
    o[t] = a0;
    o[t + 256] = a1;
    o[t + 512] = a2;
}

// ---------------- launcher --------------------------------------------------
extern "C" void kernel_launch(void* const* d_in, const int* in_sizes, int n_in,
                              void* d_out, int out_size) {
    const float* x     = (const float*)d_in[0];
    const float* W_enc = (const float*)d_in[1];
    const float* b_enc = (const float*)d_in[2];
    const float* W_dec = (const float*)d_in[3];
    const float* b_dec = (const float*)d_in[4];
    float* out = (float*)d_out;

    sub_bdec_kernel<<<(BATCH * DIM + 255) / 256, 256>>>(x, b_dec);

    dim3 tgrid(FEAT / 32, DIM / 32);
    dim3 tblk(32, 8);
    transpose_wdec_kernel<<<tgrid, tblk>>>(W_dec);

    dim3 ggrid(FEAT / GBN, BATCH / GBM);
    encode_gemm_kernel<<<ggrid, 256>>>(W_enc, b_enc);

    topk_kernel<<<BATCH, 256>>>();

    decode_kernel<<<BATCH, 256>>>(b_dec, out);
}

// round 3
// speedup vs baseline: 1.3794x; 1.3794x over previous
#include <cuda_runtime.h>
#include <cuda_bf16.h>
#include <cstdint>

// Problem constants
#define BATCH 4096
#define DIM   768
#define FEAT  16384
#define TOPK  64

// GEMM tile config
#define BM 256
#define BN 128
#define BK 16
#define NSTAGE 4
#define GTHREADS 512
#define NCHUNK (DIM / BK)          // 48
// padded smem row stride (floats) for conflict-free fragment loads
#define RS 20
#define STAGE_BYTES ((BM + BN) * RS * 4)   // 30720
#define SMEM_BYTES (NSTAGE * STAGE_BYTES)  // 122880

// ---------------- scratch (device globals; no allocation allowed) ----------
__device__ float g_xc[BATCH * DIM];                       // x - b_dec
__device__ float g_pre[(size_t)BATCH * FEAT];             // pre-activations (256 MB)
__device__ float g_WdT[(size_t)FEAT * DIM];               // W_dec transposed (50 MB)
__device__ int   g_tidx[BATCH * TOPK];
__device__ float g_tval[BATCH * TOPK];

// ---------------- helpers ---------------------------------------------------
__device__ __forceinline__ uint32_t smem_u32(const void* p) {
    uint32_t a;
    asm("{ .reg .u64 t; cvta.to.shared.u64 t, %1; cvt.u32.u64 %0, t; }" : "=r"(a) : "l"(p));
    return a;
}
__device__ __forceinline__ void split_tf32(float v, uint32_t& hi, uint32_t& lo) {
    uint32_t h;
    asm("cvt.rna.tf32.f32 %0, %1;" : "=r"(h) : "f"(v));
    float r = v - __uint_as_float(h);
    uint32_t l;
    asm("cvt.rna.tf32.f32 %0, %1;" : "=r"(l) : "f"(r));
    hi = h; lo = l;
}
__device__ __forceinline__ void mma_tf32(float* c, const uint32_t* a, const uint32_t* b) {
    asm volatile(
        "mma.sync.aligned.m16n8k8.row.col.f32.tf32.tf32.f32 "
        "{%0,%1,%2,%3}, {%4,%5,%6,%7}, {%8,%9}, {%0,%1,%2,%3};\n"
        : "+f"(c[0]), "+f"(c[1]), "+f"(c[2]), "+f"(c[3])
        : "r"(a[0]), "r"(a[1]), "r"(a[2]), "r"(a[3]), "r"(b[0]), "r"(b[1]));
}
#define CP_ASYNC16(dst, src) \
    asm volatile("cp.async.cg.shared.global [%0], [%1], 16;" :: "r"(dst), "l"(src))
#define CP_COMMIT() asm volatile("cp.async.commit_group;" ::: "memory")
#define CP_WAIT(n)  asm volatile("cp.async.wait_group %0;" :: "n"(n) : "memory")

// ---------------- kernel 1: xc = x - b_dec ----------------------------------
__global__ void __launch_bounds__(256) sub_bdec_kernel(const float* __restrict__ x,
                                                       const float* __restrict__ b_dec) {
    int i = blockIdx.x * 256 + threadIdx.x;
    if (i < BATCH * DIM) g_xc[i] = x[i] - b_dec[i % DIM];
}

// ---------------- kernel 2: transpose W_dec [D,F] -> [F,D] ------------------
__global__ void transpose_wdec_kernel(const float* __restrict__ Wd) {
    __shared__ float tile[32][33];
    int f0 = blockIdx.x * 32;
    int d0 = blockIdx.y * 32;
    int tx = threadIdx.x, ty = threadIdx.y;   // block (32, 8)
    #pragma unroll
    for (int i = 0; i < 32; i += 8)
        tile[ty + i][tx] = Wd[(size_t)(d0 + ty + i) * FEAT + f0 + tx];
    __syncthreads();
    #pragma unroll
    for (int i = 0; i < 32; i += 8)
        g_WdT[(size_t)(f0 + ty + i) * DIM + d0 + tx] = tile[tx][ty + i];
}

// ---------------- kernel 3: encode GEMM, 3xTF32 mma.sync --------------------
// g_pre[m,n] = sum_k xc[m,k] * W_enc[n,k] + b_enc[n]
// block 256x128, 512 threads (16 warps, 4x4), warp tile 64x32 (4x4 m16n8k8)
__device__ __forceinline__ void load_stage(uint32_t sbase, int chunk, int m0, int n0,
                                           const float* __restrict__ Wenc, int tid) {
    const int k0 = chunk * BK;
    #pragma unroll
    for (int p = 0; p < 3; p++) {
        int s = tid + p * GTHREADS;          // 0..1535
        if (s < 1024) {
            int r = s >> 2, q = s & 3;       // A: 256 rows x 4 segs
            const float* src = g_xc + (size_t)(m0 + r) * DIM + k0 + q * 4;
            CP_ASYNC16(sbase + r * (RS * 4) + q * 16, src);
        } else {
            int s2 = s - 1024;
            int r = s2 >> 2, q = s2 & 3;     // B: 128 rows x 4 segs
            const float* src = Wenc + (size_t)(n0 + r) * DIM + k0 + q * 4;
            CP_ASYNC16(sbase + BM * (RS * 4) + r * (RS * 4) + q * 16, src);
        }
    }
    CP_COMMIT();
}

__global__ void __launch_bounds__(GTHREADS, 1) encode_gemm_kernel(
    const float* __restrict__ Wenc, const float* __restrict__ bias) {
    extern __shared__ __align__(16) char smem[];
    const int tid = threadIdx.x;
    const int lane = tid & 31;
    const int wid = tid >> 5;
    const int warp_m = wid >> 2;     // 0..3 -> 64-row slab
    const int warp_n = wid & 3;      // 0..3 -> 32-col slab
    const int m0 = blockIdx.y * BM;
    const int n0 = blockIdx.x * BN;
    const uint32_t smem_base = smem_u32(smem);

    float acc[4][4][4];
    #pragma unroll
    for (int i = 0; i < 4; i++)
        #pragma unroll
        for (int j = 0; j < 4; j++)
            #pragma unroll
            for (int r = 0; r < 4; r++) acc[i][j][r] = 0.f;

    // prologue: prefetch 3 stages
    #pragma unroll
    for (int c = 0; c < NSTAGE - 1; c++)
        load_stage(smem_base + c * STAGE_BYTES, c, m0, n0, Wenc, tid);

    const int lr = lane >> 2;     // 0..7
    const int lc = lane & 3;      // 0..3

    for (int chunk = 0; chunk < NCHUNK; chunk++) {
        CP_WAIT(NSTAGE - 2);
        __syncthreads();

        const int st = chunk & (NSTAGE - 1);
        const float* sA = (const float*)(smem + st * STAGE_BYTES);
        const float* sB = (const float*)(smem + st * STAGE_BYTES + BM * RS * 4);

        #pragma unroll
        for (int k8 = 0; k8 < 2; k8++) {
            const int kb = k8 * 8;
            uint32_t b0[4][2], b1[4][2];
            #pragma unroll
            for (int nt = 0; nt < 4; nt++) {
                int n = warp_n * 32 + nt * 8 + lr;
                float v0 = sB[n * RS + kb + lc];
                float v1 = sB[n * RS + kb + 4 + lc];
                split_tf32(v0, b0[nt][0], b1[nt][0]);
                split_tf32(v1, b0[nt][1], b1[nt][1]);
            }
            #pragma unroll
            for (int mt = 0; mt < 4; mt++) {
                int m = warp_m * 64 + mt * 16 + lr;
                float va0 = sA[m * RS + kb + lc];
                float va1 = sA[(m + 8) * RS + kb + lc];
                float va2 = sA[m * RS + kb + 4 + lc];
                float va3 = sA[(m + 8) * RS + kb + 4 + lc];
                uint32_t a0[4], a1[4];
                split_tf32(va0, a0[0], a1[0]);
                split_tf32(va1, a0[1], a1[1]);
                split_tf32(va2, a0[2], a1[2]);
                split_tf32(va3, a0[3], a1[3]);
                #pragma unroll
                for (int nt = 0; nt < 4; nt++) mma_tf32(acc[mt][nt], a0, b0[nt]);
                #pragma unroll
                for (int nt = 0; nt < 4; nt++) mma_tf32(acc[mt][nt], a0, b1[nt]);
                #pragma unroll
                for (int nt = 0; nt < 4; nt++) mma_tf32(acc[mt][nt], a1, b0[nt]);
            }
        }

        int next = chunk + NSTAGE - 1;
        if (next < NCHUNK)
            load_stage(smem_base + (next & (NSTAGE - 1)) * STAGE_BYTES, next, m0, n0, Wenc, tid);
        __syncthreads();
    }

    // epilogue: acc + bias -> g_pre
    #pragma unroll
    for (int mt = 0; mt < 4; mt++) {
        #pragma unroll
        for (int nt = 0; nt < 4; nt++) {
            int row = m0 + warp_m * 64 + mt * 16 + lr;
            int col = n0 + warp_n * 32 + nt * 8 + 2 * lc;
            float2 bv = *(const float2*)&bias[col];
            float2 o0 = make_float2(acc[mt][nt][0] + bv.x, acc[mt][nt][1] + bv.y);
            float2 o1 = make_float2(acc[mt][nt][2] + bv.x, acc[mt][nt][3] + bv.y);
            *(float2*)&g_pre[(size_t)row * FEAT + col] = o0;
            *(float2*)&g_pre[(size_t)(row + 8) * FEAT + col] = o1;
        }
    }
}

// ---------------- helpers for topk ------------------------------------------
__device__ __forceinline__ unsigned fkey(float v) {
    unsigned u = __float_as_uint(v);
    return (u & 0x80000000u) ? ~u : (u | 0x80000000u);
}
__device__ __forceinline__ float key_to_float(unsigned k) {
    unsigned u = (k & 0x80000000u) ? (k & 0x7fffffffu) : ~k;
    return __uint_as_float(u);
}

// ---------------- kernel 4: exact top-64 per row (radix select) -------------
__global__ void __launch_bounds__(256) topk_kernel() {
    const int row = blockIdx.x;
    const float* p = g_pre + (size_t)row * FEAT;
    const int tid = threadIdx.x;

    __shared__ unsigned hist[2048];
    __shared__ unsigned sh_digit, sh_need;
    __shared__ int cnt, eqn;
    __shared__ int eqbuf[256];

    unsigned prefix = 0;
    unsigned need = TOPK;

    const int shifts[3]  = {21, 10, 0};
    const int bitsArr[3] = {11, 11, 10};

    for (int lvl = 0; lvl < 3; lvl++) {
        const int shift = shifts[lvl];
        const int nb = 1 << bitsArr[lvl];
        for (int i = tid; i < 2048; i += 256) hist[i] = 0;
        __syncthreads();
        for (int i = tid; i < FEAT; i += 256) {
            unsigned key = fkey(p[i]);
            bool ok = (lvl == 0) || ((key >> (shift + bitsArr[lvl])) == prefix);
            if (ok) atomicAdd(&hist[(key >> shift) & (nb - 1)], 1u);
        }
        __syncthreads();
        if (tid == 0) {
            unsigned cum = 0, dig = 0, rem = need;
            for (int b = nb - 1; b >= 0; b--) {
                unsigned h = hist[b];
                if (cum + h >= need) { dig = (unsigned)b; rem = need - cum; break; }
                cum += h;
            }
            sh_digit = dig;
            sh_need = rem;
        }
        __syncthreads();
        prefix = (prefix << bitsArr[lvl]) | sh_digit;
        need = sh_need;
        __syncthreads();
    }

    const unsigned T = prefix;
    if (tid == 0) { cnt = 0; eqn = 0; }
    __syncthreads();

    for (int i = tid; i < FEAT; i += 256) {
        unsigned key = fkey(p[i]);
        if (key > T) {
            int s = atomicAdd(&cnt, 1);
            g_tidx[row * TOPK + s] = i;
            g_tval[row * TOPK + s] = p[i];
        } else if (key == T) {
            int e = atomicAdd(&eqn, 1);
            if (e < 256) eqbuf[e] = i;
        }
    }
    __syncthreads();

    if (tid == 0) {
        int ne = eqn; if (ne > 256) ne = 256;
        for (int a = 1; a < ne; a++) {
            int v = eqbuf[a]; int b = a - 1;
            while (b >= 0 && eqbuf[b] > v) { eqbuf[b + 1] = eqbuf[b]; b--; }
            eqbuf[b + 1] = v;
        }
        float tv = key_to_float(T);
        int base = cnt;
        for (int j = 0; j < (int)need; j++) {
            g_tidx[row * TOPK + base + j] = eqbuf[j];
            g_tval[row * TOPK + base + j] = tv;
        }
    }
}

// ---------------- kernel 5: sparse decode ------------------------------------
__global__ void __launch_bounds__(256) decode_kernel(const float* __restrict__ b_dec,
                                                     float* __restrict__ out) {
    const int row = blockIdx.x;
    const int t = threadIdx.x;
    __shared__ int   sidx[TOPK];
    __shared__ float sval[TOPK];
    if (t < TOPK) {
        sidx[t] = g_tidx[row * TOPK + t];
        sval[t] = g_tval[row * TOPK + t];
    }
    __syncthreads();

    float a0 = b_dec[t];
    float a1 = b_dec[t + 256];
    float a2 = b_dec[t + 512];
    #pragma unroll 4
    for (int k = 0; k < TOPK; k++) {
        const float* w = g_WdT + (size_t)sidx[k] * DIM;
        float v = sval[k];
        a0 += v * w[t];
        a1 += v * w[t + 256];
        a2 += v * w[t + 512];
    }
    float* o = out + (size_t)row * DIM;
    o[t] = a0;
    o[t + 256] = a1;
    o[t + 512] = a2;
}

// ---------------- launcher ----------------------------------------------------
extern "C" void kernel_launch(void* const* d_in, const int* in_sizes, int n_in,
                              void* d_out, int out_size) {
    const float* x     = (const float*)d_in[0];
    const float* W_enc = (const float*)d_in[1];
    const float* b_enc = (const float*)d_in[2];
    const float* W_dec = (const float*)d_in[3];
    const float* b_dec = (const float*)d_in[4];
    float* out = (float*)d_out;

    sub_bdec_kernel<<<(BATCH * DIM + 255) / 256, 256>>>(x, b_dec);

    dim3 tgrid(FEAT / 32, DIM / 32);
    dim3 tblk(32, 8);
    transpose_wdec_kernel<<<tgrid, tblk>>>(W_dec);

    static bool attr_set = false;
    if (!attr_set) {
        cudaFuncSetAttribute(encode_gemm_kernel,
                             cudaFuncAttributeMaxDynamicSharedMemorySize, SMEM_BYTES);
        attr_set = true;
    }
    dim3 ggrid(FEAT / BN, BATCH / BM);
    encode_gemm_kernel<<<ggrid, GTHREADS, SMEM_BYTES>>>(W_enc, b_enc);

    topk_kernel<<<BATCH, 256>>>();

    decode_kernel<<<BATCH, 256>>>(b_dec, out);
}

// round 4
// speedup vs baseline: 1.5644x; 1.1341x over previous
#include <cuda_runtime.h>
#include <cuda_bf16.h>
#include <cstdint>

// Problem constants
#define BATCH 4096
#define DIM   768
#define FEAT  16384
#define TOPK  64

// GEMM tile config
#define BM 256
#define BN 128
#define BK 16
#define NSTAGE 3
#define GTHREADS 512
#define NCHUNK (DIM / BK)          // 48
#define RS 20                      // padded smem row stride (floats)
// stage layout (uint32 offsets): A_hi | A_lo | B_hi | B_lo
#define OFF_AH 0
#define OFF_AL (BM * RS)                  // 5120
#define OFF_BH (2 * BM * RS)              // 10240
#define OFF_BL (2 * BM * RS + BN * RS)    // 12800
#define STAGE_U32 (2 * BM * RS + 2 * BN * RS)   // 15360
#define STAGE_BYTES (STAGE_U32 * 4)             // 61440
#define SMEM_BYTES (NSTAGE * STAGE_BYTES)       // 184320

// topk smem: keys[FEAT] + hist[2048]
#define TK_SMEM_BYTES ((FEAT + 2048) * 4)       // 73728

// ---------------- scratch (device globals; no allocation allowed) ----------
__device__ float g_pre[(size_t)BATCH * FEAT];             // pre-activations (256 MB)
__device__ float g_WdT[(size_t)FEAT * DIM];               // W_dec transposed (50 MB)
__device__ int   g_tidx[BATCH * TOPK];
__device__ float g_tval[BATCH * TOPK];
// tf32 hi/lo splits (bit patterns)
__device__ uint32_t g_xh[BATCH * DIM];
__device__ uint32_t g_xl[BATCH * DIM];
__device__ uint32_t g_wh[(size_t)FEAT * DIM];
__device__ uint32_t g_wl[(size_t)FEAT * DIM];

// ---------------- helpers ---------------------------------------------------
__device__ __forceinline__ uint32_t smem_u32(const void* p) {
    uint32_t a;
    asm("{ .reg .u64 t; cvta.to.shared.u64 t, %1; cvt.u32.u64 %0, t; }" : "=r"(a) : "l"(p));
    return a;
}
__device__ __forceinline__ void split_tf32(float v, uint32_t& hi, uint32_t& lo) {
    uint32_t h;
    asm("cvt.rna.tf32.f32 %0, %1;" : "=r"(h) : "f"(v));
    float r = v - __uint_as_float(h);
    uint32_t l;
    asm("cvt.rna.tf32.f32 %0, %1;" : "=r"(l) : "f"(r));
    hi = h; lo = l;
}
__device__ __forceinline__ void mma_tf32(float* c, const uint32_t* a, const uint32_t* b) {
    asm volatile(
        "mma.sync.aligned.m16n8k8.row.col.f32.tf32.tf32.f32 "
        "{%0,%1,%2,%3}, {%4,%5,%6,%7}, {%8,%9}, {%0,%1,%2,%3};\n"
        : "+f"(c[0]), "+f"(c[1]), "+f"(c[2]), "+f"(c[3])
        : "r"(a[0]), "r"(a[1]), "r"(a[2]), "r"(a[3]), "r"(b[0]), "r"(b[1]));
}
#define CP_ASYNC16(dst, src) \
    asm volatile("cp.async.cg.shared.global [%0], [%1], 16;" :: "r"(dst), "l"(src))
#define CP_COMMIT() asm volatile("cp.async.commit_group;" ::: "memory")
#define CP_WAIT(n)  asm volatile("cp.async.wait_group %0;" :: "n"(n) : "memory")

// ---------------- kernel: tf32 split of (x - b_dec) -------------------------
__global__ void __launch_bounds__(256) split_x_kernel(const float* __restrict__ x,
                                                      const float* __restrict__ b_dec) {
    int i = blockIdx.x * 256 + threadIdx.x;
    if (i >= BATCH * DIM) return;
    float a = x[i] - b_dec[i % DIM];
    uint32_t h, l;
    split_tf32(a, h, l);
    g_xh[i] = h; g_xl[i] = l;
}

// ---------------- kernel: tf32 split of W_enc --------------------------------
__global__ void __launch_bounds__(256) split_w_kernel(const float* __restrict__ W) {
    size_t i = (size_t)blockIdx.x * 256 + threadIdx.x;
    if (i >= (size_t)FEAT * DIM) return;
    uint32_t h, l;
    split_tf32(W[i], h, l);
    g_wh[i] = h; g_wl[i] = l;
}

// ---------------- kernel: transpose W_dec [D,F] -> [F,D] ---------------------
__global__ void transpose_wdec_kernel(const float* __restrict__ Wd) {
    __shared__ float tile[32][33];
    int f0 = blockIdx.x * 32;
    int d0 = blockIdx.y * 32;
    int tx = threadIdx.x, ty = threadIdx.y;   // block (32, 8)
    #pragma unroll
    for (int i = 0; i < 32; i += 8)
        tile[ty + i][tx] = Wd[(size_t)(d0 + ty + i) * FEAT + f0 + tx];
    __syncthreads();
    #pragma unroll
    for (int i = 0; i < 32; i += 8)
        g_WdT[(size_t)(f0 + ty + i) * DIM + d0 + tx] = tile[tx][ty + i];
}

// ---------------- kernel: encode GEMM, 3xTF32 mma.sync -----------------------
// g_pre[m,n] = sum_k xc[m,k] * W_enc[n,k] + b_enc[n]
// block 256x128, 512 threads (16 warps 4x4), warp tile 64x32 (4x4 m16n8k8)
__device__ __forceinline__ void load_stage(uint32_t sbase, int chunk, int m0, int n0, int tid) {
    const int k0 = chunk * BK;
    #pragma unroll
    for (int p = 0; p < 6; p++) {
        int s = tid + p * GTHREADS;          // 0..3071
        if (s < 1024) {                      // A_hi: 256 rows x 4 segs
            int r = s >> 2, q = s & 3;
            CP_ASYNC16(sbase + (OFF_AH + r * RS + q * 4) * 4,
                       g_xh + (size_t)(m0 + r) * DIM + k0 + q * 4);
        } else if (s < 2048) {               // A_lo
            int s2 = s - 1024;
            int r = s2 >> 2, q = s2 & 3;
            CP_ASYNC16(sbase + (OFF_AL + r * RS + q * 4) * 4,
                       g_xl + (size_t)(m0 + r) * DIM + k0 + q * 4);
        } else if (s < 2560) {               // B_hi: 128 rows x 4 segs
            int s2 = s - 2048;
            int r = s2 >> 2, q = s2 & 3;
            CP_ASYNC16(sbase + (OFF_BH + r * RS + q * 4) * 4,
                       g_wh + (size_t)(n0 + r) * DIM + k0 + q * 4);
        } else {                             // B_lo
            int s2 = s - 2560;
            int r = s2 >> 2, q = s2 & 3;
            CP_ASYNC16(sbase + (OFF_BL + r * RS + q * 4) * 4,
                       g_wl + (size_t)(n0 + r) * DIM + k0 + q * 4);
        }
    }
    CP_COMMIT();
}

__global__ void __launch_bounds__(GTHREADS, 1) encode_gemm_kernel(
    const float* __restrict__ bias) {
    extern __shared__ __align__(16) char smem[];
    const int tid = threadIdx.x;
    const int lane = tid & 31;
    const int wid = tid >> 5;
    const int warp_m = wid >> 2;     // 0..3 -> 64-row slab
    const int warp_n = wid & 3;      // 0..3 -> 32-col slab
    const int m0 = blockIdx.y * BM;
    const int n0 = blockIdx.x * BN;
    const uint32_t smem_base = smem_u32(smem);

    float acc[4][4][4];
    #pragma unroll
    for (int i = 0; i < 4; i++)
        #pragma unroll
        for (int j = 0; j < 4; j++)
            #pragma unroll
            for (int r = 0; r < 4; r++) acc[i][j][r] = 0.f;

    #pragma unroll
    for (int c = 0; c < NSTAGE - 1; c++)
        load_stage(smem_base + c * STAGE_BYTES, c, m0, n0, tid);

    const int lr = lane >> 2;     // 0..7
    const int lc = lane & 3;      // 0..3

    for (int chunk = 0; chunk < NCHUNK; chunk++) {
        CP_WAIT(NSTAGE - 2);
        __syncthreads();

        const int st = chunk % NSTAGE;
        const uint32_t* sb = (const uint32_t*)(smem + st * STAGE_BYTES);
        const uint32_t* sAh = sb + OFF_AH;
        const uint32_t* sAl = sb + OFF_AL;
        const uint32_t* sBh = sb + OFF_BH;
        const uint32_t* sBl = sb + OFF_BL;

        #pragma unroll
        for (int k8 = 0; k8 < 2; k8++) {
            const int kb = k8 * 8;
            uint32_t bh[4][2], bl[4][2];
            #pragma unroll
            for (int nt = 0; nt < 4; nt++) {
                int n = warp_n * 32 + nt * 8 + lr;
                bh[nt][0] = sBh[n * RS + kb + lc];
                bh[nt][1] = sBh[n * RS + kb + 4 + lc];
                bl[nt][0] = sBl[n * RS + kb + lc];
                bl[nt][1] = sBl[n * RS + kb + 4 + lc];
            }
            #pragma unroll
            for (int mt = 0; mt < 4; mt++) {
                int m = warp_m * 64 + mt * 16 + lr;
                uint32_t ah[4], al[4];
                ah[0] = sAh[m * RS + kb + lc];
                ah[1] = sAh[(m + 8) * RS + kb + lc];
                ah[2] = sAh[m * RS + kb + 4 + lc];
                ah[3] = sAh[(m + 8) * RS + kb + 4 + lc];
                al[0] = sAl[m * RS + kb + lc];
                al[1] = sAl[(m + 8) * RS + kb + lc];
                al[2] = sAl[m * RS + kb + 4 + lc];
                al[3] = sAl[(m + 8) * RS + kb + 4 + lc];
                #pragma unroll
                for (int nt = 0; nt < 4; nt++) mma_tf32(acc[mt][nt], ah, bh[nt]);
                #pragma unroll
                for (int nt = 0; nt < 4; nt++) mma_tf32(acc[mt][nt], ah, bl[nt]);
                #pragma unroll
                for (int nt = 0; nt < 4; nt++) mma_tf32(acc[mt][nt], al, bh[nt]);
            }
        }

        int next = chunk + NSTAGE - 1;
        if (next < NCHUNK)
            load_stage(smem_base + (next % NSTAGE) * STAGE_BYTES, next, m0, n0, tid);
        __syncthreads();
    }

    // epilogue: acc + bias -> g_pre
    #pragma unroll
    for (int mt = 0; mt < 4; mt++) {
        #pragma unroll
        for (int nt = 0; nt < 4; nt++) {
            int row = m0 + warp_m * 64 + mt * 16 + lr;
            int col = n0 + warp_n * 32 + nt * 8 + 2 * lc;
            float2 bv = *(const float2*)&bias[col];
            float2 o0 = make_float2(acc[mt][nt][0] + bv.x, acc[mt][nt][1] + bv.y);
            float2 o1 = make_float2(acc[mt][nt][2] + bv.x, acc[mt][nt][3] + bv.y);
            *(float2*)&g_pre[(size_t)row * FEAT + col] = o0;
            *(float2*)&g_pre[(size_t)(row + 8) * FEAT + col] = o1;
        }
    }
}

// ---------------- helpers for topk ------------------------------------------
__device__ __forceinline__ unsigned fkey(float v) {
    unsigned u = __float_as_uint(v);
    return (u & 0x80000000u) ? ~u : (u | 0x80000000u);
}
__device__ __forceinline__ float key_to_float(unsigned k) {
    unsigned u = (k & 0x80000000u) ? (k & 0x7fffffffu) : ~k;
    return __uint_as_float(u);
}

// ---------------- kernel: exact top-64 per row (radix select, smem-cached) ---
__global__ void __launch_bounds__(256) topk_kernel() {
    extern __shared__ uint32_t tk[];        // keys[FEAT] then hist[2048]
    uint32_t* keys = tk;
    uint32_t* hist = tk + FEAT;

    const int row = blockIdx.x;
    const int tid = threadIdx.x;

    __shared__ unsigned tsum[256];
    __shared__ unsigned sh_digit, sh_need;
    __shared__ int cnt, eqn;
    __shared__ int eqbuf[256];

    for (int i = tid; i < 2048; i += 256) hist[i] = 0;
    __syncthreads();

    // single global read: build keys + level-0 histogram (bits 31..21)
    const float4* p4 = (const float4*)(g_pre + (size_t)row * FEAT);
    #pragma unroll
    for (int it = 0; it < 16; it++) {
        int i = tid + it * 256;             // float4 index (4096 total)
        float4 v = p4[i];
        unsigned k0 = fkey(v.x), k1 = fkey(v.y), k2 = fkey(v.z), k3 = fkey(v.w);
        keys[i * 4 + 0] = k0; keys[i * 4 + 1] = k1;
        keys[i * 4 + 2] = k2; keys[i * 4 + 3] = k3;
        atomicAdd(&hist[k0 >> 21], 1u);
        atomicAdd(&hist[k1 >> 21], 1u);
        atomicAdd(&hist[k2 >> 21], 1u);
        atomicAdd(&hist[k3 >> 21], 1u);
    }
    __syncthreads();

    unsigned prefix = 0;
    unsigned need = TOPK;
    const int shifts[3]  = {21, 10, 0};
    const int bitsArr[3] = {11, 11, 10};

    for (int lvl = 0; lvl < 3; lvl++) {
        const int shift = shifts[lvl];
        const int bits = bitsArr[lvl];
        const int nb = 1 << bits;

        if (lvl > 0) {
            for (int i = tid; i < nb; i += 256) hist[i] = 0;
            __syncthreads();
            for (int it = 0; it < FEAT / 256; it++) {
                unsigned key = keys[tid + it * 256];
                if ((key >> (shift + bits)) == prefix)
                    atomicAdd(&hist[(key >> shift) & (nb - 1)], 1u);
            }
            __syncthreads();
        }

        // parallel digit selection (descending)
        const int stride = nb / 256;
        unsigned s = 0;
        #pragma unroll 4
        for (int j = 0; j < stride; j++) s += hist[tid * stride + j];
        tsum[tid] = s;
        __syncthreads();
        if (tid == 0) {
            unsigned cum = 0;
            int t = 255;
            for (; t >= 0; t--) {
                if (cum + tsum[t] >= need) break;
                cum += tsum[t];
            }
            unsigned dig = 0;
            for (int b = (t + 1) * stride - 1; b >= t * stride; b--) {
                unsigned h = hist[b];
                if (cum + h >= need) { dig = (unsigned)b; break; }
                cum += h;
            }
            sh_digit = dig;
            sh_need = need - cum;
        }
        __syncthreads();
        prefix = (prefix << bits) | sh_digit;
        need = sh_need;
        __syncthreads();
    }

    const unsigned T = prefix;              // exact key of K-th largest
    if (tid == 0) { cnt = 0; eqn = 0; }
    __syncthreads();

    for (int it = 0; it < FEAT / 256; it++) {
        int i = tid + it * 256;
        unsigned key = keys[i];
        if (key > T) {
            int s2 = atomicAdd(&cnt, 1);
            g_tidx[row * TOPK + s2] = i;
            g_tval[row * TOPK + s2] = key_to_float(key);
        } else if (key == T) {
            int e = atomicAdd(&eqn, 1);
            if (e < 256) eqbuf[e] = i;
        }
    }
    __syncthreads();

    if (tid == 0) {
        int ne = eqn; if (ne > 256) ne = 256;
        for (int a = 1; a < ne; a++) {
            int v = eqbuf[a]; int b = a - 1;
            while (b >= 0 && eqbuf[b] > v) { eqbuf[b + 1] = eqbuf[b]; b--; }
            eqbuf[b + 1] = v;
        }
        float tv = key_to_float(T);
        int base = cnt;
        for (int j = 0; j < (int)need; j++) {
            g_tidx[row * TOPK + base + j] = eqbuf[j];
            g_tval[row * TOPK + base + j] = tv;
        }
    }
}

// ---------------- kernel: sparse decode ---------------------------------------
__global__ void __launch_bounds__(256) decode_kernel(const float* __restrict__ b_dec,
                                                     float* __restrict__ out) {
    const int row = blockIdx.x;
    const int t = threadIdx.x;
    __shared__ int   sidx[TOPK];
    __shared__ float sval[TOPK];
    if (t < TOPK) {
        sidx[t] = g_tidx[row * TOPK + t];
        sval[t] = g_tval[row * TOPK + t];
    }
    __syncthreads();

    float a0 = b_dec[t];
    float a1 = b_dec[t + 256];
    float a2 = b_dec[t + 512];
    #pragma unroll 4
    for (int k = 0; k < TOPK; k++) {
        const float* w = g_WdT + (size_t)sidx[k] * DIM;
        float v = sval[k];
        a0 += v * w[t];
        a1 += v * w[t + 256];
        a2 += v * w[t + 512];
    }
    float* o = out + (size_t)row * DIM;
    o[t] = a0;
    o[t + 256] = a1;
    o[t + 512] = a2;
}

// ---------------- launcher -----------------------------------------------------
extern "C" void kernel_launch(void* const* d_in, const int* in_sizes, int n_in,
                              void* d_out, int out_size) {
    const float* x     = (const float*)d_in[0];
    const float* W_enc = (const float*)d_in[1];
    const float* b_enc = (const float*)d_in[2];
    const float* W_dec = (const float*)d_in[3];
    const float* b_dec = (const float*)d_in[4];
    float* out = (float*)d_out;

    cudaFuncSetAttribute(encode_gemm_kernel,
                         cudaFuncAttributeMaxDynamicSharedMemorySize, SMEM_BYTES);
    cudaFuncSetAttribute(topk_kernel,
                         cudaFuncAttributeMaxDynamicSharedMemorySize, TK_SMEM_BYTES);

    split_x_kernel<<<(BATCH * DIM + 255) / 256, 256>>>(x, b_dec);
    split_w_kernel<<<(int)(((size_t)FEAT * DIM + 255) / 256), 256>>>(W_enc);

    dim3 tgrid(FEAT / 32, DIM / 32);
    dim3 tblk(32, 8);
    transpose_wdec_kernel<<<tgrid, tblk>>>(W_dec);

    dim3 ggrid(FEAT / BN, BATCH / BM);
    encode_gemm_kernel<<<ggrid, GTHREADS, SMEM_BYTES>>>(b_enc);

    topk_kernel<<<BATCH, 256, TK_SMEM_BYTES>>>();

    decode_kernel<<<BATCH, 256>>>(b_dec, out);
}